// round 1
// baseline (speedup 1.0000x reference)
#include <cuda_runtime.h>
#include <math.h>
#include <stdint.h>

#define HIDDEN   4096
#define CODE_DIM 256
#define KCODES   4096
#define NTOK     16384      // B*S = 4*4096
#define BETA     0.25f

#define OUT_EMBED_ELEMS ((long long)NTOK * HIDDEN)   // 67108864
#define LOSS_BLOCKS 128

// ---------------- scratch (device globals; no allocations allowed) ----------
__device__ __align__(16) float g_z[(size_t)NTOK * CODE_DIM];   // 16 MB
__device__ float g_e2[KCODES];
__device__ float g_x2[NTOK];
__device__ unsigned long long g_best[NTOK];
__device__ int   g_idx[NTOK];
__device__ float g_loss_part[LOSS_BLOCKS];
__device__ float g_prior_part[LOSS_BLOCKS];

// ---------------- init: best = +inf pack ------------------------------------
__global__ void k_init_best() {
    int t = blockIdx.x * blockDim.x + threadIdx.x;
    if (t < NTOK) g_best[t] = 0xFFFFFFFFFFFFFFFFull;
}

// ---------------- row sum-of-squares (warp per row) --------------------------
__global__ void k_rowsq(const float* __restrict__ rows, float* __restrict__ out, int nrows) {
    int warp = (blockIdx.x * blockDim.x + threadIdx.x) >> 5;
    int lane = threadIdx.x & 31;
    if (warp >= nrows) return;
    const float* r = rows + (size_t)warp * CODE_DIM;
    float s = 0.f;
    #pragma unroll
    for (int d = lane; d < CODE_DIM; d += 32) { float v = r[d]; s = fmaf(v, v, s); }
    #pragma unroll
    for (int o = 16; o; o >>= 1) s += __shfl_xor_sync(0xFFFFFFFFu, s, o);
    if (lane == 0) out[warp] = s;
}

// ---------------- generic fp32 NT GEMM: C[M,N] = A[M,K] * B[N,K]^T + bias ----
// 64x64 tile, BK=16, 256 threads, 4x4 microtile. Optional row gather on A.
template <bool GATHER>
__global__ __launch_bounds__(256)
void k_gemm_nt(const float* __restrict__ A, const float* __restrict__ B,
               const float* __restrict__ bias, float* __restrict__ C,
               int M, int N, int K, const int* __restrict__ gidx)
{
    __shared__ float As[16][64];
    __shared__ float Bs[16][64];
    const int tid  = threadIdx.x;
    const int tx   = tid & 15;
    const int ty   = tid >> 4;
    const int lrow = tid >> 2;
    const int seg  = tid & 3;

    const int arow = blockIdx.y * 64 + lrow;
    const int brow = blockIdx.x * 64 + lrow;
    const long long asrc = GATHER ? (long long)gidx[arow] : (long long)arow;
    const float4* Ap = (const float4*)(A + asrc * (long long)K) + seg;
    const float4* Bp = (const float4*)(B + (long long)brow * K) + seg;

    float acc[4][4];
    #pragma unroll
    for (int i = 0; i < 4; i++)
        #pragma unroll
        for (int j = 0; j < 4; j++) acc[i][j] = 0.f;

    for (int k0 = 0; k0 < K; k0 += 16) {
        float4 av = Ap[k0 >> 2];
        float4 bv = Bp[k0 >> 2];
        As[seg * 4 + 0][lrow] = av.x;
        As[seg * 4 + 1][lrow] = av.y;
        As[seg * 4 + 2][lrow] = av.z;
        As[seg * 4 + 3][lrow] = av.w;
        Bs[seg * 4 + 0][lrow] = bv.x;
        Bs[seg * 4 + 1][lrow] = bv.y;
        Bs[seg * 4 + 2][lrow] = bv.z;
        Bs[seg * 4 + 3][lrow] = bv.w;
        __syncthreads();
        #pragma unroll
        for (int kk = 0; kk < 16; kk++) {
            float4 a = *(const float4*)&As[kk][ty * 4];
            float4 b = *(const float4*)&Bs[kk][tx * 4];
            acc[0][0] = fmaf(a.x, b.x, acc[0][0]);
            acc[0][1] = fmaf(a.x, b.y, acc[0][1]);
            acc[0][2] = fmaf(a.x, b.z, acc[0][2]);
            acc[0][3] = fmaf(a.x, b.w, acc[0][3]);
            acc[1][0] = fmaf(a.y, b.x, acc[1][0]);
            acc[1][1] = fmaf(a.y, b.y, acc[1][1]);
            acc[1][2] = fmaf(a.y, b.z, acc[1][2]);
            acc[1][3] = fmaf(a.y, b.w, acc[1][3]);
            acc[2][0] = fmaf(a.z, b.x, acc[2][0]);
            acc[2][1] = fmaf(a.z, b.y, acc[2][1]);
            acc[2][2] = fmaf(a.z, b.z, acc[2][2]);
            acc[2][3] = fmaf(a.z, b.w, acc[2][3]);
            acc[3][0] = fmaf(a.w, b.x, acc[3][0]);
            acc[3][1] = fmaf(a.w, b.y, acc[3][1]);
            acc[3][2] = fmaf(a.w, b.z, acc[3][2]);
            acc[3][3] = fmaf(a.w, b.w, acc[3][3]);
        }
        __syncthreads();
    }

    const int crow0 = blockIdx.y * 64 + ty * 4;
    const int ccol0 = blockIdx.x * 64 + tx * 4;
    float4 bb = *(const float4*)&bias[ccol0];
    #pragma unroll
    for (int i = 0; i < 4; i++) {
        float4 o;
        o.x = acc[i][0] + bb.x;
        o.y = acc[i][1] + bb.y;
        o.z = acc[i][2] + bb.z;
        o.w = acc[i][3] + bb.w;
        *(float4*)&C[(long long)(crow0 + i) * N + ccol0] = o;
    }
}

// ---------------- dist GEMM + fused argmin -----------------------------------
// xe = z[M,256] * codebook[K,256]^T ; dist = (x2 + e2) - 2*xe ; packed atomicMin
__global__ __launch_bounds__(256)
void k_dist(const float* __restrict__ Z, const float* __restrict__ CB)
{
    __shared__ float As[16][64];
    __shared__ float Bs[16][64];
    const int tid  = threadIdx.x;
    const int tx   = tid & 15;
    const int ty   = tid >> 4;
    const int lrow = tid >> 2;
    const int seg  = tid & 3;

    const int arow = blockIdx.y * 64 + lrow;   // token
    const int brow = blockIdx.x * 64 + lrow;   // code
    const float4* Ap = (const float4*)(Z  + (long long)arow * CODE_DIM) + seg;
    const float4* Bp = (const float4*)(CB + (long long)brow * CODE_DIM) + seg;

    float acc[4][4];
    #pragma unroll
    for (int i = 0; i < 4; i++)
        #pragma unroll
        for (int j = 0; j < 4; j++) acc[i][j] = 0.f;

    #pragma unroll
    for (int k0 = 0; k0 < CODE_DIM; k0 += 16) {
        float4 av = Ap[k0 >> 2];
        float4 bv = Bp[k0 >> 2];
        As[seg * 4 + 0][lrow] = av.x;
        As[seg * 4 + 1][lrow] = av.y;
        As[seg * 4 + 2][lrow] = av.z;
        As[seg * 4 + 3][lrow] = av.w;
        Bs[seg * 4 + 0][lrow] = bv.x;
        Bs[seg * 4 + 1][lrow] = bv.y;
        Bs[seg * 4 + 2][lrow] = bv.z;
        Bs[seg * 4 + 3][lrow] = bv.w;
        __syncthreads();
        #pragma unroll
        for (int kk = 0; kk < 16; kk++) {
            float4 a = *(const float4*)&As[kk][ty * 4];
            float4 b = *(const float4*)&Bs[kk][tx * 4];
            acc[0][0] = fmaf(a.x, b.x, acc[0][0]);
            acc[0][1] = fmaf(a.x, b.y, acc[0][1]);
            acc[0][2] = fmaf(a.x, b.z, acc[0][2]);
            acc[0][3] = fmaf(a.x, b.w, acc[0][3]);
            acc[1][0] = fmaf(a.y, b.x, acc[1][0]);
            acc[1][1] = fmaf(a.y, b.y, acc[1][1]);
            acc[1][2] = fmaf(a.y, b.z, acc[1][2]);
            acc[1][3] = fmaf(a.y, b.w, acc[1][3]);
            acc[2][0] = fmaf(a.z, b.x, acc[2][0]);
            acc[2][1] = fmaf(a.z, b.y, acc[2][1]);
            acc[2][2] = fmaf(a.z, b.z, acc[2][2]);
            acc[2][3] = fmaf(a.z, b.w, acc[2][3]);
            acc[3][0] = fmaf(a.w, b.x, acc[3][0]);
            acc[3][1] = fmaf(a.w, b.y, acc[3][1]);
            acc[3][2] = fmaf(a.w, b.z, acc[3][2]);
            acc[3][3] = fmaf(a.w, b.w, acc[3][3]);
        }
        __syncthreads();
    }

    // epilogue: dist = (x2 + e2) - 2*xe, replicated rounding chain of the reference
    const int trow0 = blockIdx.y * 64 + ty * 4;
    const int ccol0 = blockIdx.x * 64 + tx * 4;
    float e2v[4];
    #pragma unroll
    for (int j = 0; j < 4; j++) e2v[j] = g_e2[ccol0 + j];

    #pragma unroll
    for (int i = 0; i < 4; i++) {
        const int t = trow0 + i;
        const float x2v = g_x2[t];
        unsigned long long best = 0xFFFFFFFFFFFFFFFFull;
        #pragma unroll
        for (int j = 0; j < 4; j++) {
            float t1 = x2v + e2v[j];                    // R(x2 + e2)
            float dist = fmaf(-2.0f, acc[i][j], t1);    // R(t1 - 2*xe)  (2*xe exact)
            unsigned long long p =
                ((unsigned long long)__float_as_uint(dist) << 32) |
                (unsigned int)(ccol0 + j);
            best = (p < best) ? p : best;
        }
        // reduce across the 16 lanes (tx) that share this token row
        #pragma unroll
        for (int o = 8; o; o >>= 1) {
            unsigned long long q = __shfl_xor_sync(0xFFFFFFFFu, best, o);
            best = (q < best) ? q : best;
        }
        if (tx == 0) atomicMin(&g_best[t], best);
    }
}

// ---------------- extract idx + write idx floats -----------------------------
__global__ void k_extract(float* __restrict__ out_idx) {
    int t = blockIdx.x * blockDim.x + threadIdx.x;
    if (t >= NTOK) return;
    unsigned long long p = g_best[t];
    int id = (int)(unsigned int)(p & 0xFFFFFFFFull);
    g_idx[t] = id;
    out_idx[t] = (float)id;
}

// ---------------- loss partials ----------------------------------------------
__global__ __launch_bounds__(256)
void k_loss(const float* __restrict__ CB, const float* __restrict__ prior) {
    const int b = blockIdx.x;
    const int tid = threadIdx.x;
    float acc = 0.f;
    const int t0 = b * (NTOK / LOSS_BLOCKS);
    for (int t = t0; t < t0 + (NTOK / LOSS_BLOCKS); t++) {
        int id = g_idx[t];
        float zv = g_z[(size_t)t * CODE_DIM + tid];
        float ev = CB[(size_t)id * CODE_DIM + tid];
        float d = zv - ev;
        acc = fmaf(d, d, acc);
    }
    __shared__ float sm[256];
    sm[tid] = acc;
    __syncthreads();
    for (int s = 128; s; s >>= 1) {
        if (tid < s) sm[tid] += sm[tid + s];
        __syncthreads();
    }
    if (tid == 0) {
        g_loss_part[b] = sm[0];
        float ps = 0.f;
        for (int t = t0; t < t0 + (NTOK / LOSS_BLOCKS); t++) ps += prior[g_idx[t]];
        g_prior_part[b] = ps;
    }
}

// ---------------- finalize: lse, bits, vq_loss --------------------------------
__global__ __launch_bounds__(256)
void k_final(const float* __restrict__ prior, float* __restrict__ out) {
    __shared__ float sm[256];
    const int tid = threadIdx.x;

    float m = -INFINITY;
    for (int i = tid; i < KCODES; i += 256) m = fmaxf(m, prior[i]);
    sm[tid] = m; __syncthreads();
    for (int s = 128; s; s >>= 1) { if (tid < s) sm[tid] = fmaxf(sm[tid], sm[tid + s]); __syncthreads(); }
    const float mx = sm[0]; __syncthreads();

    float se = 0.f;
    for (int i = tid; i < KCODES; i += 256) se += expf(prior[i] - mx);
    sm[tid] = se; __syncthreads();
    for (int s = 128; s; s >>= 1) { if (tid < s) sm[tid] += sm[tid + s]; __syncthreads(); }
    const float lse = mx + logf(sm[0]); __syncthreads();

    float lp = (tid < LOSS_BLOCKS) ? g_loss_part[tid] : 0.f;
    sm[tid] = lp; __syncthreads();
    for (int s = 128; s; s >>= 1) { if (tid < s) sm[tid] += sm[tid + s]; __syncthreads(); }
    const float loss_sum = sm[0]; __syncthreads();

    float pp = (tid < LOSS_BLOCKS) ? g_prior_part[tid] : 0.f;
    sm[tid] = pp; __syncthreads();
    for (int s = 128; s; s >>= 1) { if (tid < s) sm[tid] += sm[tid + s]; __syncthreads(); }
    const float prior_sum = sm[0];

    if (tid == 0) {
        float bits = ((float)NTOK * lse - prior_sum) / logf(2.0f);
        float vq   = (1.0f + BETA) * loss_sum / ((float)NTOK * (float)CODE_DIM);
        out[OUT_EMBED_ELEMS]     = bits;
        out[OUT_EMBED_ELEMS + 1] = vq;
    }
}

// ---------------- launch -------------------------------------------------------
extern "C" void kernel_launch(void* const* d_in, const int* in_sizes, int n_in,
                              void* d_out, int out_size)
{
    const float* embed   = (const float*)d_in[0];   // [NTOK, HIDDEN]
    const float* W_pre   = (const float*)d_in[1];   // [CODE_DIM, HIDDEN]
    const float* b_pre   = (const float*)d_in[2];   // [CODE_DIM]
    const float* cb      = (const float*)d_in[3];   // [KCODES, CODE_DIM]
    const float* W_post  = (const float*)d_in[4];   // [HIDDEN, CODE_DIM]
    const float* b_post  = (const float*)d_in[5];   // [HIDDEN]
    const float* prior   = (const float*)d_in[6];   // [KCODES]
    float* out = (float*)d_out;

    float* z_ptr;   cudaGetSymbolAddress((void**)&z_ptr,   g_z);
    float* e2_ptr;  cudaGetSymbolAddress((void**)&e2_ptr,  g_e2);
    float* x2_ptr;  cudaGetSymbolAddress((void**)&x2_ptr,  g_x2);
    int*   idx_ptr; cudaGetSymbolAddress((void**)&idx_ptr, g_idx);

    // 1) init argmin state
    k_init_best<<<NTOK / 256, 256>>>();
    // 2) e2 per code
    k_rowsq<<<(KCODES * 32 + 255) / 256, 256>>>(cb, e2_ptr, KCODES);
    // 3) z = embed @ W_pre^T + b_pre
    {
        dim3 grid(CODE_DIM / 64, NTOK / 64);
        k_gemm_nt<false><<<grid, 256>>>(embed, W_pre, b_pre, z_ptr,
                                        NTOK, CODE_DIM, HIDDEN, nullptr);
    }
    // 4) x2 per token
    k_rowsq<<<(NTOK * 32 + 255) / 256, 256>>>(z_ptr, x2_ptr, NTOK);
    // 5) fused dist + argmin
    {
        dim3 grid(KCODES / 64, NTOK / 64);
        k_dist<<<grid, 256>>>(z_ptr, cb);
    }
    // 6) extract idx + write idx output
    k_extract<<<NTOK / 256, 256>>>(out + OUT_EMBED_ELEMS + 2);
    // 7) embed_hat = codebook[idx] @ W_post^T + b_post
    {
        dim3 grid(HIDDEN / 64, NTOK / 64);
        k_gemm_nt<true><<<grid, 256>>>(cb, W_post, b_post, out,
                                       NTOK, HIDDEN, CODE_DIM, idx_ptr);
    }
    // 8) loss partials
    k_loss<<<LOSS_BLOCKS, 256>>>(cb, prior);
    // 9) scalars
    k_final<<<1, 256>>>(prior, out);

    (void)in_sizes; (void)n_in; (void)out_size;
}